// round 10
// baseline (speedup 1.0000x reference)
#include <cuda_runtime.h>

#define BATCH 2048
#define IN_SZ 40960
#define HID 256
#define ROW_F4 (IN_SZ / 4)          // 10240 uint4 per one-hot row
#define ROW_ITERS (ROW_F4 / 256)    // 40 uint4-groups per thread per perspective
#define GRID (BATCH / 2)            // 1024 CTAs, 2 rows each -> single wave
#define HSTRIDE 516                 // hid row stride (bank-conflict-free)

__device__ float g_ftw_t[(size_t)IN_SZ * HID];   // 41.9 MB transposed weights

// ---------------------------------------------------------------------------
// Kernel 1: transpose ft_w [256, 40960] -> g_ftw_t [40960, 256]
// ---------------------------------------------------------------------------
__global__ __launch_bounds__(256) void transpose_ft(const float* __restrict__ ft_w) {
    __shared__ float tile[32][33];
    int x = blockIdx.x * 32 + threadIdx.x;
    int y = blockIdx.y * 32 + threadIdx.y;
#pragma unroll
    for (int k = 0; k < 32; k += 8)
        tile[threadIdx.y + k][threadIdx.x] = ft_w[(size_t)(y + k) * IN_SZ + x];
    __syncthreads();
    int ox = blockIdx.y * 32 + threadIdx.x;
    int oy = blockIdx.x * 32 + threadIdx.y;
#pragma unroll
    for (int k = 0; k < 32; k += 8)
        g_ftw_t[(size_t)(oy + k) * HID + ox] = tile[threadIdx.x][threadIdx.y + k];
}

// ---------------------------------------------------------------------------
// Kernel 2: two rows per CTA, software-pipelined.
//   P1: scan row0.  P2: scan row1 with row0 gather interleaved (DRAM stays
//   busy through the gather).  Tail (row1 gather + 2-row MLP) exposed once.
// ---------------------------------------------------------------------------
__global__ __launch_bounds__(256, 7) void nnue_fused(
    const float* __restrict__ white, const float* __restrict__ black,
    const float* __restrict__ stm,
    const float* __restrict__ ft_b,
    const float* __restrict__ l1w, const float* __restrict__ l1b,
    const float* __restrict__ l2w, const float* __restrict__ l2b,
    const float* __restrict__ l3w, const float* __restrict__ l3b,
    float* __restrict__ out)
{
    const int b0  = blockIdx.x * 2;
    const int b1  = b0 + 1;
    const int tid = threadIdx.x;

    __shared__ int    cnt[2][2];         // [row][persp]
    __shared__ int    idx[2][2][32];     // [row][persp][slot]
    __shared__ float4 red[2][4][64];     // [persp][fgroup][col] (reused per row)
    __shared__ float  hid[2][HSTRIDE];   // ordered 512-activations per row
    __shared__ float  x1s[2][32];
    __shared__ float  x2s[2][32];

    if (tid < 4) ((int*)cnt)[tid] = 0;
    __syncthreads();

    const int c  = tid & 63;
    const int fg = tid >> 6;
    const float4* __restrict__ ftw4 = reinterpret_cast<const float4*>(g_ftw_t);

    // ---- Phase 1: scan row0 (both perspectives), batch-4 streaming ----
#pragma unroll
    for (int p = 0; p < 2; ++p) {
        const uint4* src = reinterpret_cast<const uint4*>(p ? black : white)
                         + (size_t)b0 * ROW_F4;
        for (int it = 0; it < ROW_ITERS; it += 4) {
            uint4 f[4];
#pragma unroll
            for (int u = 0; u < 4; ++u)
                f[u] = __ldcs(&src[(it + u) * 256 + tid]);
#pragma unroll
            for (int u = 0; u < 4; ++u) {
                if (f[u].x | f[u].y | f[u].z | f[u].w) {
                    int base = ((it + u) * 256 + tid) * 4;
                    if (f[u].x) { int s = atomicAdd(&cnt[0][p], 1); idx[0][p][s] = base + 0; }
                    if (f[u].y) { int s = atomicAdd(&cnt[0][p], 1); idx[0][p][s] = base + 1; }
                    if (f[u].z) { int s = atomicAdd(&cnt[0][p], 1); idx[0][p][s] = base + 2; }
                    if (f[u].w) { int s = atomicAdd(&cnt[0][p], 1); idx[0][p][s] = base + 3; }
                }
            }
        }
    }
    __syncthreads();

    const int wc0 = cnt[0][0];
    const int bc0 = cnt[0][1];

    // ---- Phase 2: scan row1, one row0-gather step per iteration ----
    float4 aw = make_float4(0.f, 0.f, 0.f, 0.f);
    float4 ab = make_float4(0.f, 0.f, 0.f, 0.f);
    int g = 0;
#pragma unroll
    for (int p = 0; p < 2; ++p) {
        const uint4* src = reinterpret_cast<const uint4*>(p ? black : white)
                         + (size_t)b1 * ROW_F4;
        for (int it = 0; it < ROW_ITERS; it += 4) {
            uint4 f[4];
#pragma unroll
            for (int u = 0; u < 4; ++u)
                f[u] = __ldcs(&src[(it + u) * 256 + tid]);
            // one gather step for row0 (scan loads above are already in flight)
            if (g < 8) {
                int k = fg + 4 * g;
                if (k < wc0) {
                    float4 v = ftw4[(size_t)idx[0][0][k] * 64 + c];
                    aw.x += v.x; aw.y += v.y; aw.z += v.z; aw.w += v.w;
                }
            } else if (g < 16) {
                int k = fg + 4 * (g - 8);
                if (k < bc0) {
                    float4 v = ftw4[(size_t)idx[0][1][k] * 64 + c];
                    ab.x += v.x; ab.y += v.y; ab.z += v.z; ab.w += v.w;
                }
            }
            ++g;
#pragma unroll
            for (int u = 0; u < 4; ++u) {
                if (f[u].x | f[u].y | f[u].z | f[u].w) {
                    int base = ((it + u) * 256 + tid) * 4;
                    if (f[u].x) { int s = atomicAdd(&cnt[1][p], 1); idx[1][p][s] = base + 0; }
                    if (f[u].y) { int s = atomicAdd(&cnt[1][p], 1); idx[1][p][s] = base + 1; }
                    if (f[u].z) { int s = atomicAdd(&cnt[1][p], 1); idx[1][p][s] = base + 2; }
                    if (f[u].w) { int s = atomicAdd(&cnt[1][p], 1); idx[1][p][s] = base + 3; }
                }
            }
        }
    }
    red[0][fg][c] = aw;
    red[1][fg][c] = ab;
    __syncthreads();

    const int wc1 = cnt[1][0];
    const int bc1 = cnt[1][1];

    // ---- Tail: gather row1 (regs) ----
    aw = make_float4(0.f, 0.f, 0.f, 0.f);
    ab = make_float4(0.f, 0.f, 0.f, 0.f);
#pragma unroll 4
    for (int j = fg; j < wc1; j += 4) {
        float4 v = ftw4[(size_t)idx[1][0][j] * 64 + c];
        aw.x += v.x; aw.y += v.y; aw.z += v.z; aw.w += v.w;
    }
#pragma unroll 4
    for (int j = fg; j < bc1; j += 4) {
        float4 v = ftw4[(size_t)idx[1][1][j] * 64 + c];
        ab.x += v.x; ab.y += v.y; ab.z += v.z; ab.w += v.w;
    }

    // reduce row0 (red currently holds row0 partials)
    const bool s0 = (stm[b0] != 0.f);
    if (tid < 128) {
        int p  = tid >> 6;
        int cc = tid & 63;
        float4 v0 = red[p][0][cc], v1 = red[p][1][cc];
        float4 v2 = red[p][2][cc], v3 = red[p][3][cc];
        float4 bi = reinterpret_cast<const float4*>(ft_b)[cc];
        int half = ((p == 0) == s0) ? 0 : 1;
        float* h = &hid[0][half * 256 + cc * 4];
        h[0] = fminf(fmaxf(v0.x + v1.x + v2.x + v3.x + bi.x, 0.f), 1.f);
        h[1] = fminf(fmaxf(v0.y + v1.y + v2.y + v3.y + bi.y, 0.f), 1.f);
        h[2] = fminf(fmaxf(v0.z + v1.z + v2.z + v3.z + bi.z, 0.f), 1.f);
        h[3] = fminf(fmaxf(v0.w + v1.w + v2.w + v3.w + bi.w, 0.f), 1.f);
    }
    __syncthreads();   // row0 partials consumed

    red[0][fg][c] = aw;
    red[1][fg][c] = ab;
    __syncthreads();

    // reduce row1
    const bool s1 = (stm[b1] != 0.f);
    if (tid < 128) {
        int p  = tid >> 6;
        int cc = tid & 63;
        float4 v0 = red[p][0][cc], v1 = red[p][1][cc];
        float4 v2 = red[p][2][cc], v3 = red[p][3][cc];
        float4 bi = reinterpret_cast<const float4*>(ft_b)[cc];
        int half = ((p == 0) == s1) ? 0 : 1;
        float* h = &hid[1][half * 256 + cc * 4];
        h[0] = fminf(fmaxf(v0.x + v1.x + v2.x + v3.x + bi.x, 0.f), 1.f);
        h[1] = fminf(fmaxf(v0.y + v1.y + v2.y + v3.y + bi.y, 0.f), 1.f);
        h[2] = fminf(fmaxf(v0.z + v1.z + v2.z + v3.z + bi.z, 0.f), 1.f);
        h[3] = fminf(fmaxf(v0.w + v1.w + v2.w + v3.w + bi.w, 0.f), 1.f);
    }
    __syncthreads();

    // ---- MLP, both rows in one pass ----
    // Layer 1: 512 -> 32; 8 threads per output = 4 lanes x 2 rows.
    {
        int k     = tid >> 3;          // output 0..31
        int s8    = tid & 7;
        int row   = s8 >> 2;           // 0 or 1
        int lane4 = s8 & 3;
        const float* w = l1w + k * 512;
        const float* h = hid[row];
        float p = 0.f;
#pragma unroll
        for (int j = lane4; j < 512; j += 4) p += h[j] * w[j];
        p += __shfl_down_sync(0xffffffffu, p, 2, 4);
        p += __shfl_down_sync(0xffffffffu, p, 1, 4);
        if (lane4 == 0) x1s[row][k] = fminf(fmaxf(p + l1b[k], 0.f), 1.f);
    }
    __syncthreads();

    // Layer 2: 32 -> 32, both rows (64 threads)
    if (tid < 64) {
        int row = tid >> 5, k = tid & 31;
        float p = l2b[k];
        const float* w = l2w + k * 32;
#pragma unroll
        for (int j = 0; j < 32; ++j) p += x1s[row][j] * w[j];
        x2s[row][k] = fminf(fmaxf(p, 0.f), 1.f);
    }
    __syncthreads();

    // Layer 3: 32 -> 1 per row (warp 0 = row0, warp 1 = row1)
    if (tid < 64) {
        int row = tid >> 5, lane = tid & 31;
        float p = x2s[row][lane] * l3w[lane];
        p += __shfl_down_sync(0xffffffffu, p, 16);
        p += __shfl_down_sync(0xffffffffu, p, 8);
        p += __shfl_down_sync(0xffffffffu, p, 4);
        p += __shfl_down_sync(0xffffffffu, p, 2);
        p += __shfl_down_sync(0xffffffffu, p, 1);
        if (lane == 0) out[b0 + row] = p + l3b[0];
    }
}

// ---------------------------------------------------------------------------
// Launch
// ---------------------------------------------------------------------------
extern "C" void kernel_launch(void* const* d_in, const int* in_sizes, int n_in,
                              void* d_out, int out_size) {
    const float* white = (const float*)d_in[0];
    const float* black = (const float*)d_in[1];
    const float* stm   = (const float*)d_in[2];
    const float* ft_w  = (const float*)d_in[3];
    const float* ft_b  = (const float*)d_in[4];
    const float* l1w   = (const float*)d_in[5];
    const float* l1b   = (const float*)d_in[6];
    const float* l2w   = (const float*)d_in[7];
    const float* l2b   = (const float*)d_in[8];
    const float* l3w   = (const float*)d_in[9];
    const float* l3b   = (const float*)d_in[10];
    float* out = (float*)d_out;

    dim3 tb(32, 8);
    dim3 tg(IN_SZ / 32, HID / 32);
    transpose_ft<<<tg, tb>>>(ft_w);

    nnue_fused<<<GRID, 256>>>(white, black, stm, ft_b,
                              l1w, l1b, l2w, l2b, l3w, l3b, out);
}

// round 11
// speedup vs baseline: 1.0519x; 1.0519x over previous
#include <cuda_runtime.h>

#define BATCH 2048
#define IN_SZ 40960
#define HID 256
#define ROW_F4 (IN_SZ / 4)          // 10240 uint4 per one-hot row
#define ROW_ITERS (ROW_F4 / 256)    // 40 uint4-groups per thread per perspective

__device__ float g_ftw_t[(size_t)IN_SZ * HID];   // 41.9 MB transposed weights

// ---------------------------------------------------------------------------
// Kernel 1: transpose ft_w [256, 40960] -> g_ftw_t [40960, 256]
// ---------------------------------------------------------------------------
__global__ __launch_bounds__(256) void transpose_ft(const float* __restrict__ ft_w) {
    __shared__ float tile[32][33];
    int x = blockIdx.x * 32 + threadIdx.x;
    int y = blockIdx.y * 32 + threadIdx.y;
#pragma unroll
    for (int k = 0; k < 32; k += 8)
        tile[threadIdx.y + k][threadIdx.x] = ft_w[(size_t)(y + k) * IN_SZ + x];
    __syncthreads();
    int ox = blockIdx.y * 32 + threadIdx.x;
    int oy = blockIdx.x * 32 + threadIdx.y;
#pragma unroll
    for (int k = 0; k < 32; k += 8)
        g_ftw_t[(size_t)(oy + k) * HID + ox] = tile[threadIdx.x][threadIdx.y + k];
}

// ---------------------------------------------------------------------------
// Kernel 2: one CTA per row (grid 2048 -> 1.73 waves keeps tail stagger).
//   Phase A: scan white (batch-4 streaming).
//   Phase B: scan black with the white gather interleaved (white indices are
//            ready; each iteration issues 4 stream loads then 1 gather step).
//   Tail:    black gather + MLP only (~half of R9's tail), hidden by stagger.
// ---------------------------------------------------------------------------
__global__ __launch_bounds__(256, 8) void nnue_fused(
    const float* __restrict__ white, const float* __restrict__ black,
    const float* __restrict__ stm,
    const float* __restrict__ ft_b,
    const float* __restrict__ l1w, const float* __restrict__ l1b,
    const float* __restrict__ l2w, const float* __restrict__ l2b,
    const float* __restrict__ l3w, const float* __restrict__ l3b,
    float* __restrict__ out)
{
    const int b   = blockIdx.x;
    const int tid = threadIdx.x;

    __shared__ int    cnt[2];
    __shared__ int    idx[2][32];
    __shared__ float4 red[2][4][64];
    __shared__ float  hid[2 * HID];
    __shared__ float  x1s[32];
    __shared__ float  x2s[32];

    if (tid < 2) cnt[tid] = 0;
    __syncthreads();

    const int c  = tid & 63;
    const int fg = tid >> 6;
    const float4* __restrict__ ftw4 = reinterpret_cast<const float4*>(g_ftw_t);

    // ---- Phase A: scan white, batch-4 streaming loads ----
    {
        const uint4* src = reinterpret_cast<const uint4*>(white) + (size_t)b * ROW_F4;
        for (int it = 0; it < ROW_ITERS; it += 4) {
            uint4 f[4];
#pragma unroll
            for (int u = 0; u < 4; ++u)
                f[u] = __ldcs(&src[(it + u) * 256 + tid]);
#pragma unroll
            for (int u = 0; u < 4; ++u) {
                if (f[u].x | f[u].y | f[u].z | f[u].w) {
                    int base = ((it + u) * 256 + tid) * 4;
                    if (f[u].x) { int s = atomicAdd(&cnt[0], 1); idx[0][s] = base + 0; }
                    if (f[u].y) { int s = atomicAdd(&cnt[0], 1); idx[0][s] = base + 1; }
                    if (f[u].z) { int s = atomicAdd(&cnt[0], 1); idx[0][s] = base + 2; }
                    if (f[u].w) { int s = atomicAdd(&cnt[0], 1); idx[0][s] = base + 3; }
                }
            }
        }
    }
    __syncthreads();
    const int wc = cnt[0];

    // ---- Phase B: scan black, white gather interleaved ----
    float4 aw = make_float4(0.f, 0.f, 0.f, 0.f);
    float4 ab = make_float4(0.f, 0.f, 0.f, 0.f);
    {
        const uint4* src = reinterpret_cast<const uint4*>(black) + (size_t)b * ROW_F4;
        int g = 0;
        for (int it = 0; it < ROW_ITERS; it += 4) {
            uint4 f[4];
#pragma unroll
            for (int u = 0; u < 4; ++u)
                f[u] = __ldcs(&src[(it + u) * 256 + tid]);
            // two white-gather steps per iteration (scan loads already in flight)
#pragma unroll
            for (int r = 0; r < 2; ++r) {
                int k = fg + 4 * g;
                if (k < wc) {
                    float4 v = ftw4[(size_t)idx[0][k] * 64 + c];
                    aw.x += v.x; aw.y += v.y; aw.z += v.z; aw.w += v.w;
                }
                ++g;
            }
#pragma unroll
            for (int u = 0; u < 4; ++u) {
                if (f[u].x | f[u].y | f[u].z | f[u].w) {
                    int base = ((it + u) * 256 + tid) * 4;
                    if (f[u].x) { int s = atomicAdd(&cnt[1], 1); idx[1][s] = base + 0; }
                    if (f[u].y) { int s = atomicAdd(&cnt[1], 1); idx[1][s] = base + 1; }
                    if (f[u].z) { int s = atomicAdd(&cnt[1], 1); idx[1][s] = base + 2; }
                    if (f[u].w) { int s = atomicAdd(&cnt[1], 1); idx[1][s] = base + 3; }
                }
            }
        }
    }
    __syncthreads();
    const int bc = cnt[1];

    // ---- Tail: black gather only ----
#pragma unroll 4
    for (int j = fg; j < bc; j += 4) {
        float4 v = ftw4[(size_t)idx[1][j] * 64 + c];
        ab.x += v.x; ab.y += v.y; ab.z += v.z; ab.w += v.w;
    }
    red[0][fg][c] = aw;
    red[1][fg][c] = ab;
    __syncthreads();

    const bool s = (stm[b] != 0.f);

    if (tid < 128) {
        int p  = tid >> 6;
        int cc = tid & 63;
        float4 v0 = red[p][0][cc], v1 = red[p][1][cc];
        float4 v2 = red[p][2][cc], v3 = red[p][3][cc];
        float4 bi = reinterpret_cast<const float4*>(ft_b)[cc];
        float4 r;
        r.x = fminf(fmaxf(v0.x + v1.x + v2.x + v3.x + bi.x, 0.f), 1.f);
        r.y = fminf(fmaxf(v0.y + v1.y + v2.y + v3.y + bi.y, 0.f), 1.f);
        r.z = fminf(fmaxf(v0.z + v1.z + v2.z + v3.z + bi.z, 0.f), 1.f);
        r.w = fminf(fmaxf(v0.w + v1.w + v2.w + v3.w + bi.w, 0.f), 1.f);
        int half = ((p == 0) == s) ? 0 : 1;
        reinterpret_cast<float4*>(hid)[half * 64 + cc] = r;
    }
    __syncthreads();

    // ---- MLP ----
    // Layer 1: 512 -> 32, 8 threads per output
    {
        int k  = tid >> 3;
        int s8 = tid & 7;
        const float* w = l1w + k * 512;
        float p = 0.f;
#pragma unroll
        for (int j = s8; j < 512; j += 8) p += hid[j] * w[j];
        p += __shfl_down_sync(0xffffffffu, p, 4, 8);
        p += __shfl_down_sync(0xffffffffu, p, 2, 8);
        p += __shfl_down_sync(0xffffffffu, p, 1, 8);
        if (s8 == 0) x1s[k] = fminf(fmaxf(p + l1b[k], 0.f), 1.f);
    }
    __syncthreads();

    // Layer 2: 32 -> 32
    if (tid < 32) {
        float p = l2b[tid];
        const float* w = l2w + tid * 32;
#pragma unroll
        for (int j = 0; j < 32; ++j) p += x1s[j] * w[j];
        x2s[tid] = fminf(fmaxf(p, 0.f), 1.f);
    }
    __syncwarp(0xffffffffu);

    // Layer 3: 32 -> 1
    if (tid < 32) {
        float p = x2s[tid] * l3w[tid];
        p += __shfl_down_sync(0xffffffffu, p, 16);
        p += __shfl_down_sync(0xffffffffu, p, 8);
        p += __shfl_down_sync(0xffffffffu, p, 4);
        p += __shfl_down_sync(0xffffffffu, p, 2);
        p += __shfl_down_sync(0xffffffffu, p, 1);
        if (tid == 0) out[b] = p + l3b[0];
    }
}

// ---------------------------------------------------------------------------
// Launch
// ---------------------------------------------------------------------------
extern "C" void kernel_launch(void* const* d_in, const int* in_sizes, int n_in,
                              void* d_out, int out_size) {
    const float* white = (const float*)d_in[0];
    const float* black = (const float*)d_in[1];
    const float* stm   = (const float*)d_in[2];
    const float* ft_w  = (const float*)d_in[3];
    const float* ft_b  = (const float*)d_in[4];
    const float* l1w   = (const float*)d_in[5];
    const float* l1b   = (const float*)d_in[6];
    const float* l2w   = (const float*)d_in[7];
    const float* l2b   = (const float*)d_in[8];
    const float* l3w   = (const float*)d_in[9];
    const float* l3b   = (const float*)d_in[10];
    float* out = (float*)d_out;

    dim3 tb(32, 8);
    dim3 tg(IN_SZ / 32, HID / 32);
    transpose_ft<<<tg, tb>>>(ft_w);

    nnue_fused<<<BATCH, 256>>>(white, black, stm, ft_b,
                               l1w, l1b, l2w, l2b, l3w, l3b, out);
}